// round 17
// baseline (speedup 1.0000x reference)
#include <cuda_runtime.h>
#include <cuda_bf16.h>
#include <cstdint>
#include <cstddef>

// Problem constants
#define Bsz   16384
#define Xlen  50
#define CINd  128
#define Hdim  128
#define NG3   384           // 3*H
#define NGEMM 512           // 3*H + H  (gates | alpha_ih)

// Scratch (device globals — no allocation in kernel_launch)
__device__ float          d_P[(size_t)Bsz * NGEMM];       // 33.5 MB
__device__ __nv_bfloat16  d_Wt_hi[NGEMM * CINd];          // W^T hi, [n][k]
__device__ __nv_bfloat16  d_Wt_lo[NGEMM * CINd];          // W^T residual
__device__ int            d_mismatch[2];

// ---------------------------------------------------------------------------
// Kernel 1: prep. Block 0: transpose+split weights to bf16 hi/lo.
//           Block 1: identity checks (writes d_mismatch directly).
// ---------------------------------------------------------------------------
__global__ __launch_bounds__(512)
void prep_kernel(const float* __restrict__ w_ih,
                 const float* __restrict__ aw_ih,
                 const float* __restrict__ w_hh,
                 const float* __restrict__ aw_hh) {
    int tid = threadIdx.x;
    if (blockIdx.x == 0) {
        for (int i = tid; i < NGEMM * CINd; i += 512) {
            int n = i >> 7, k = i & 127;
            float v = (n < NG3) ? w_ih[k * NG3 + n]
                                : aw_ih[k * Hdim + (n - NG3)];
            __nv_bfloat16 h = __float2bfloat16(v);
            d_Wt_hi[i] = h;
            d_Wt_lo[i] = __float2bfloat16(v - __bfloat162float(h));
        }
    } else {
        __shared__ int bad0, bad1;
        if (tid == 0) { bad0 = 0; bad1 = 0; }
        __syncthreads();
        bool b = false;
        for (int i = tid; i < 12288; i += 512) {
            float4 v = reinterpret_cast<const float4*>(w_hh)[i];
            int f = i * 4, k = f / NG3, c = f - k * NG3;
            b |= (v.x != ((((c    ) & 127) == k) ? 1.f : 0.f))
               | (v.y != ((((c + 1) & 127) == k) ? 1.f : 0.f))
               | (v.z != ((((c + 2) & 127) == k) ? 1.f : 0.f))
               | (v.w != ((((c + 3) & 127) == k) ? 1.f : 0.f));
        }
        if (b) atomicOr(&bad0, 1);
        b = false;
        for (int i = tid; i < 4096; i += 512) {
            float4 v = reinterpret_cast<const float4*>(aw_hh)[i];
            int f = i * 4, k = f >> 7, c = f & 127;
            b |= (v.x != (((c    ) == k) ? 1.f : 0.f))
               | (v.y != (((c + 1) == k) ? 1.f : 0.f))
               | (v.z != (((c + 2) == k) ? 1.f : 0.f))
               | (v.w != (((c + 3) == k) ? 1.f : 0.f));
        }
        if (b) atomicOr(&bad1, 1);
        __syncthreads();
        if (tid == 0) { d_mismatch[0] = bad0; d_mismatch[1] = bad1; }
    }
}

// ---------------------------------------------------------------------------
// Kernel 2: bf16-split GEMM on mma.sync (HMMA; valid under compute_103).
//   P[16384,512] = inp[16384,128] @ W,  D = AhBh + AhBl + AlBh (fp32 acc)
// grid (128,4): block = 128x128 tile. 8 warps as 2(M) x 4(N), warp 64x32.
// Padded smem rows (136 bf16) make all fragment LDS.32 bank-conflict-free:
//   bank = (row*68 + ks*8 + tig) % 32 -> 4*g + tig, distinct for g<8,tig<4.
// ---------------------------------------------------------------------------
#define PITCH 136
#define ATILE (128 * PITCH)                 // bf16 elements per buffer
#define GEMM_SMEM (4 * ATILE * 2)           // 139264 bytes

__device__ __forceinline__ void mma_bf16(float& c0, float& c1, float& c2, float& c3,
                                         uint32_t a0, uint32_t a1, uint32_t a2, uint32_t a3,
                                         uint32_t b0, uint32_t b1) {
    asm volatile(
        "mma.sync.aligned.m16n8k16.row.col.f32.bf16.bf16.f32 "
        "{%0,%1,%2,%3}, {%4,%5,%6,%7}, {%8,%9}, {%0,%1,%2,%3};"
        : "+f"(c0), "+f"(c1), "+f"(c2), "+f"(c3)
        : "r"(a0), "r"(a1), "r"(a2), "r"(a3), "r"(b0), "r"(b1));
}

__global__ __launch_bounds__(256)
void gemm_kernel(const float* __restrict__ A) {
    extern __shared__ __align__(16) char smem[];
    __nv_bfloat16* Ah = reinterpret_cast<__nv_bfloat16*>(smem);
    __nv_bfloat16* Al = Ah + ATILE;
    __nv_bfloat16* Bh = Al + ATILE;
    __nv_bfloat16* Bl = Bh + ATILE;

    const int tid  = threadIdx.x;
    const int wid  = tid >> 5, lane = tid & 31;
    const int g    = lane >> 2, tig = lane & 3;
    const int wm   = wid & 1;          // 0..1 : 64-row slab
    const int wn   = wid >> 1;         // 0..3 : 32-col slab
    const int m0   = blockIdx.x * 128;
    const int nt4  = blockIdx.y;       // N-tile 0..3

    // Stage A hi/lo: 128 rows x 64 float2
    for (int i = tid; i < 8192; i += 256) {
        int m = i >> 6, kp = i & 63;
        float2 v = *reinterpret_cast<const float2*>(
            &A[(size_t)(m0 + m) * CINd + kp * 2]);
        __nv_bfloat162 hh, ll;
        hh.x = __float2bfloat16(v.x); hh.y = __float2bfloat16(v.y);
        ll.x = __float2bfloat16(v.x - __bfloat162float(hh.x));
        ll.y = __float2bfloat16(v.y - __bfloat162float(hh.y));
        *reinterpret_cast<__nv_bfloat162*>(&Ah[m * PITCH + kp * 2]) = hh;
        *reinterpret_cast<__nv_bfloat162*>(&Al[m * PITCH + kp * 2]) = ll;
    }
    // Stage B hi/lo: 128 n-rows x 64 uint32 (pre-transposed [n][k])
    {
        const uint32_t* wh = reinterpret_cast<const uint32_t*>(d_Wt_hi) + nt4 * 8192;
        const uint32_t* wl = reinterpret_cast<const uint32_t*>(d_Wt_lo) + nt4 * 8192;
        for (int i = tid; i < 8192; i += 256) {
            int n = i >> 6, kp = i & 63;
            *reinterpret_cast<uint32_t*>(&Bh[n * PITCH + kp * 2]) = wh[i];
            *reinterpret_cast<uint32_t*>(&Bl[n * PITCH + kp * 2]) = wl[i];
        }
    }
    __syncthreads();

    float acc[4][4][4];
#pragma unroll
    for (int mt = 0; mt < 4; mt++)
#pragma unroll
        for (int nt = 0; nt < 4; nt++)
#pragma unroll
            for (int q = 0; q < 4; q++) acc[mt][nt][q] = 0.0f;

#pragma unroll
    for (int ks = 0; ks < 8; ks++) {
        const int kb = ks * 16 + tig * 2;
        uint32_t ah[4][4], al[4][4], bh[4][2], bl[4][2];
#pragma unroll
        for (int mt = 0; mt < 4; mt++) {
            int r0 = (wm * 64 + mt * 16 + g) * PITCH;
            int r8 = r0 + 8 * PITCH;
            ah[mt][0] = *reinterpret_cast<const uint32_t*>(&Ah[r0 + kb]);
            ah[mt][1] = *reinterpret_cast<const uint32_t*>(&Ah[r8 + kb]);
            ah[mt][2] = *reinterpret_cast<const uint32_t*>(&Ah[r0 + kb + 8]);
            ah[mt][3] = *reinterpret_cast<const uint32_t*>(&Ah[r8 + kb + 8]);
            al[mt][0] = *reinterpret_cast<const uint32_t*>(&Al[r0 + kb]);
            al[mt][1] = *reinterpret_cast<const uint32_t*>(&Al[r8 + kb]);
            al[mt][2] = *reinterpret_cast<const uint32_t*>(&Al[r0 + kb + 8]);
            al[mt][3] = *reinterpret_cast<const uint32_t*>(&Al[r8 + kb + 8]);
        }
#pragma unroll
        for (int nt = 0; nt < 4; nt++) {
            int n0 = (wn * 32 + nt * 8 + g) * PITCH;
            bh[nt][0] = *reinterpret_cast<const uint32_t*>(&Bh[n0 + kb]);
            bh[nt][1] = *reinterpret_cast<const uint32_t*>(&Bh[n0 + kb + 8]);
            bl[nt][0] = *reinterpret_cast<const uint32_t*>(&Bl[n0 + kb]);
            bl[nt][1] = *reinterpret_cast<const uint32_t*>(&Bl[n0 + kb + 8]);
        }
#pragma unroll
        for (int mt = 0; mt < 4; mt++)
#pragma unroll
            for (int nt = 0; nt < 4; nt++) {
                float* c = acc[mt][nt];
                mma_bf16(c[0], c[1], c[2], c[3],
                         ah[mt][0], ah[mt][1], ah[mt][2], ah[mt][3],
                         bh[nt][0], bh[nt][1]);
                mma_bf16(c[0], c[1], c[2], c[3],
                         ah[mt][0], ah[mt][1], ah[mt][2], ah[mt][3],
                         bl[nt][0], bl[nt][1]);
                mma_bf16(c[0], c[1], c[2], c[3],
                         al[mt][0], al[mt][1], al[mt][2], al[mt][3],
                         bh[nt][0], bh[nt][1]);
            }
    }

    // Epilogue: c0,c1 -> (row, col..col+1); c2,c3 -> (row+8, ...)
#pragma unroll
    for (int mt = 0; mt < 4; mt++) {
        int row = m0 + wm * 64 + mt * 16 + g;
#pragma unroll
        for (int nt = 0; nt < 4; nt++) {
            int col = nt4 * 128 + wn * 32 + nt * 8 + tig * 2;
            float* c = acc[mt][nt];
            *reinterpret_cast<float2*>(&d_P[(size_t)row * NGEMM + col]) =
                make_float2(c[0], c[1]);
            *reinterpret_cast<float2*>(&d_P[(size_t)(row + 8) * NGEMM + col]) =
                make_float2(c[2], c[3]);
        }
    }
}

// ---------------------------------------------------------------------------
// Kernel 3: fused skip-softmax-LSTM (validated R13/R15)
// ---------------------------------------------------------------------------
__device__ __forceinline__ float fsigmoid(float z) {
    float t;
    asm("tanh.approx.f32 %0, %1;" : "=f"(t) : "f"(z * 0.5f));
    return fmaf(0.5f, t, 0.5f);
}

__global__ __launch_bounds__(128)
void main_kernel(const float* __restrict__ skip_c,
                 const int*   __restrict__ skip_count,
                 const float* __restrict__ h0,
                 const float* __restrict__ w_hh,
                 const float* __restrict__ bias,
                 const float* __restrict__ aw_hh,
                 const float* __restrict__ a_bias,
                 float* __restrict__ out) {
    __shared__ float sh[Hdim];

    const int b = blockIdx.x;
    const int h = threadIdx.x;
    const int cnt = skip_count[b];

    const float* P = d_P + (size_t)b * NGEMM;
    const float* srow = skip_c + (size_t)b * Xlen * Hdim;

    const float pre = P[NG3 + h] + a_bias[h];

    float den0 = 0.f, den1 = 0.f, num0 = 0.f, num1 = 0.f;

    if (d_mismatch[1] == 0) {
        // FAST PATH: alpha_weight_hh == I
        int x = 0;
        for (; x + 4 <= cnt; x += 4) {
            float s0 = srow[(x + 0) * Hdim + h];
            float s1 = srow[(x + 1) * Hdim + h];
            float s2 = srow[(x + 2) * Hdim + h];
            float s3 = srow[(x + 3) * Hdim + h];
            float e0 = __expf(fsigmoid(pre + s0));
            float e1 = __expf(fsigmoid(pre + s1));
            float e2 = __expf(fsigmoid(pre + s2));
            float e3 = __expf(fsigmoid(pre + s3));
            den0 += e0 + e2;  den1 += e1 + e3;
            num0 = fmaf(s0, e0, num0); num1 = fmaf(s1, e1, num1);
            num0 = fmaf(s2, e2, num0); num1 = fmaf(s3, e3, num1);
        }
        for (; x < cnt; x++) {
            float s = srow[x * Hdim + h];
            float e = __expf(fsigmoid(pre + s));
            den0 += e;
            num0 = fmaf(s, e, num0);
        }
    } else {
        // GENERIC PATH: full matvec per skip row
        for (int x = 0; x < cnt; x++) {
            __syncthreads();
            sh[h] = srow[x * Hdim + h];
            __syncthreads();
            float accm = 0.0f;
#pragma unroll 8
            for (int k = 0; k < Hdim; k++)
                accm = fmaf(sh[k], aw_hh[k * Hdim + h], accm);
            float s = sh[h];
            float e = __expf(fsigmoid(pre + accm));
            den0 += e;
            num0 = fmaf(s, e, num0);
        }
    }
    float denom = den0 + den1, num = num0 + num1;

    float hh0, hh1, hh2;
    if (d_mismatch[0] == 0) {
        float hv = h0[(size_t)b * Hdim + h];
        hh0 = hh1 = hh2 = hv;
    } else {
        __syncthreads();
        sh[h] = h0[(size_t)b * Hdim + h];
        __syncthreads();
        hh0 = hh1 = hh2 = 0.0f;
        for (int k = 0; k < Hdim; k++) {
            float hv = sh[k];
            hh0 = fmaf(hv, w_hh[k * NG3 + h], hh0);
            hh1 = fmaf(hv, w_hh[k * NG3 + Hdim + h], hh1);
            hh2 = fmaf(hv, w_hh[k * NG3 + 2 * Hdim + h], hh2);
        }
    }

    float gi = P[h]            + hh0 + bias[h];
    float go = P[Hdim + h]     + hh1 + bias[Hdim + h];
    float gg = P[2 * Hdim + h] + hh2 + bias[2 * Hdim + h];

    float iv = fsigmoid(gi);
    float ov = fsigmoid(go);
    float gv = tanhf(gg);
    float ei = __expf(iv);

    float c1 = __fdividef(fmaf(gv, ei, num), ei + denom);
    float h1 = ov * tanhf(c1);

    out[(size_t)b * Hdim + h] = h1;
    out[(size_t)Bsz * Hdim + (size_t)b * Hdim + h] = c1;
}

// ---------------------------------------------------------------------------
// kernel_launch — 3 launches
// ---------------------------------------------------------------------------
extern "C" void kernel_launch(void* const* d_in, const int* in_sizes, int n_in,
                              void* d_out, int out_size) {
    const float* inp        = (const float*)d_in[0];
    const float* skip_c     = (const float*)d_in[1];
    const int*   skip_count = (const int*)  d_in[2];
    const float* h0         = (const float*)d_in[3];
    const float* w_ih       = (const float*)d_in[5];
    const float* w_hh       = (const float*)d_in[6];
    const float* bias       = (const float*)d_in[7];
    const float* aw_ih      = (const float*)d_in[8];
    const float* aw_hh      = (const float*)d_in[9];
    const float* a_bias     = (const float*)d_in[10];
    float* out = (float*)d_out;

    cudaFuncSetAttribute(gemm_kernel,
                         cudaFuncAttributeMaxDynamicSharedMemorySize,
                         GEMM_SMEM);

    prep_kernel<<<2, 512>>>(w_ih, aw_ih, w_hh, aw_hh);
    gemm_kernel<<<dim3(Bsz / 128, 4), 256, GEMM_SMEM>>>(inp);
    main_kernel<<<Bsz, Hdim>>>(skip_c, skip_count, h0, w_hh, bias,
                               aw_hh, a_bias, out);
}